// round 3
// baseline (speedup 1.0000x reference)
#include <cuda_runtime.h>
#include <cstddef>

#define TT 64
#define LL 512
#define BB 512
#define START_TAG 62
#define STOP_TAG  63

// Scratch (allocation-free requirement).
__device__ float g_partials[BB];
__device__ int   g_count;          // zero-init; reset by last block each launch

__device__ __forceinline__ void fma2(unsigned long long& acc,
                                     unsigned long long p,
                                     unsigned long long q) {
    asm("fma.rn.f32x2 %0, %1, %2, %0;" : "+l"(acc) : "l"(p), "l"(q));
}
__device__ __forceinline__ void add2(unsigned long long& a, unsigned long long b) {
    asm("add.rn.f32x2 %0, %0, %1;" : "+l"(a) : "l"(b));
}
__device__ __forceinline__ float2 unpack2(unsigned long long v) {
    float2 r;
    asm("mov.b64 {%0, %1}, %2;" : "=f"(r.x), "=f"(r.y) : "l"(v));
    return r;
}
__device__ __forceinline__ unsigned long long pack2(float lo, float hi) {
    unsigned long long v;
    asm("mov.b64 %0, {%1, %2};" : "=l"(v) : "f"(lo), "f"(hi));
    return v;
}

__device__ __forceinline__ float dot64(const float* __restrict__ qbuf,
                                       const unsigned long long* __restrict__ P2) {
    const ulonglong2* q4 = (const ulonglong2*)qbuf;
    unsigned long long a0 = 0ull, a1 = 0ull, a2 = 0ull, a3 = 0ull;
#pragma unroll
    for (int k = 0; k < TT / 8; ++k) {
        ulonglong2 v = q4[2 * k];
        ulonglong2 w = q4[2 * k + 1];
        fma2(a0, P2[4 * k + 0], v.x);
        fma2(a1, P2[4 * k + 1], v.y);
        fma2(a2, P2[4 * k + 2], w.x);
        fma2(a3, P2[4 * k + 3], w.y);
    }
    add2(a0, a1);
    add2(a2, a3);
    add2(a0, a2);
    float2 sp = unpack2(a0);
    return sp.x + sp.y;
}

__global__ void __launch_bounds__(TT, 4) crf_fused_kernel(
    const float* __restrict__ inputs,   // (B, L, T)
    const int*   __restrict__ tags,     // (B, L)
    const int*   __restrict__ mask,     // (B, L)
    const float* __restrict__ trans,    // (T, T)
    float*       __restrict__ out)
{
    const int b   = blockIdx.x;
    const int tid = threadIdx.x;

    __shared__ __align__(16) float q_sh[2][TT];
    __shared__ float dslot[2];
    __shared__ float mf_sh[LL];
    __shared__ int   tags_sh[LL];
    __shared__ float red[TT];
    __shared__ int   islast;

    // Packed exp(transition) row for destination tag = tid.
    unsigned long long P2[TT / 2];
#pragma unroll
    for (int j = 0; j < TT / 2; ++j) {
        float p0 = __expf(trans[tid * TT + 2 * j]);
        float p1 = __expf(trans[tid * TT + 2 * j + 1]);
        P2[j] = pack2(p0, p1);
    }

    // Stage mask / tags; detect all-ones mask.
    int m_and = 1;
    for (int t = tid; t < LL; t += TT) {
        int m = mask[b * LL + t];
        m_and &= (m != 0);
        mf_sh[t]   = (float)m;
        tags_sh[t] = tags[b * LL + t];
    }
    if (tid == 0) { dslot[0] = 0.0f; dslot[1] = 0.0f; }
    const int all_ones = __syncthreads_and(m_and);

    const float* emit_ptr = inputs + (size_t)b * LL * TT + tid;

    float a = (tid == START_TAG) ? 0.0f : -10000.0f;  // log-alpha (general path)
    float C = 0.0f;                                   // accumulated offset

    if (all_ones) {
        // ================= fast path: probability-space recursion =============
        // q_t[i] = s_t[i] * exp(emit_t[i]) / q_{t-1}[0];  D += log(q_{t-1}[0]).
        q_sh[0][tid] = (tid == START_TAG) ? 1.0f : 0.0f;

        // Prefetched, pre-exponentiated emissions (4 deep) — off the chain.
        float E0 = __expf(emit_ptr[0 * TT]);
        float E1 = __expf(emit_ptr[1 * TT]);
        float E2 = __expf(emit_ptr[2 * TT]);
        float E3 = __expf(emit_ptr[3 * TT]);

        float D = 0.0f;
        __syncthreads();

#pragma unroll 4
        for (int t = 0; t < LL; ++t) {
            float e_pf = (t + 4 < LL) ? emit_ptr[(t + 4) * TT] : 0.0f;
            float Epf  = __expf(e_pf);

            const int buf = t & 1;
            const float* qb = q_sh[buf];

            const float q0 = qb[0];                 // every thread has it anyway
            float r  = (t == 0) ? 1.0f : (1.0f / q0);   // off-chain divide
            float lg = __logf(q0);
            D += (t == 0) ? 0.0f : lg;              // uniform, off-chain

            const float s = dot64(qb, P2);          // the only on-chain work
            const float qn = s * (E0 * r);
            q_sh[buf ^ 1][tid] = qn;
            __syncthreads();

            E0 = E1; E1 = E2; E2 = E3; E3 = Epf;
        }

        // Convert back to log space for the shared finale.
        const float qf = q_sh[0][tid];
        a = (qf > 0.0f) ? __logf(qf) : -1.0e30f;
        if (tid == 0) dslot[0] = D;
        __syncthreads();
        C = dslot[0];
    } else {
        // ================= general masked path (log space, proven) ============
        float e_cur = emit_ptr[0];
        float e_nxt = emit_ptr[TT];
        for (int t = 0; t < LL; ++t) {
            float e_pf = (t + 2 < LL) ? emit_ptr[(t + 2) * TT] : 0.0f;

            q_sh[0][tid] = __expf(a);
            __syncthreads();

            const float mf = mf_sh[t];
            float s;
            if (mf != 0.0f) {
                s = dot64(q_sh[0], P2);
            } else {
                float acc = 0.f;
#pragma unroll
                for (int j = 0; j < TT; ++j) acc += q_sh[0][j];
                s = acc;
            }

            float d = fmaf(mf, e_cur, __logf(s));
            d = fmaxf(d, -1.0e30f);
            if (tid == 0) dslot[0] = d;
            __syncthreads();
            const float d0 = dslot[0];
            a = d - d0;
            C += d0;

            e_cur = e_nxt;
            e_nxt = e_pf;
        }
    }

    // ---- log denominator: C + logsumexp(a + trans[STOP, :]) ----
    const float term = fmaxf(a + trans[STOP_TAG * TT + tid], -1.0e30f);
    red[tid] = term;
    __syncthreads();
#pragma unroll
    for (int off = TT / 2; off > 0; off >>= 1) {
        if (tid < off) red[tid] = fmaxf(red[tid], red[tid + off]);
        __syncthreads();
    }
    const float mx = red[0];
    __syncthreads();
    red[tid] = __expf(term - mx);
    __syncthreads();
#pragma unroll
    for (int off = TT / 2; off > 0; off >>= 1) {
        if (tid < off) red[tid] += red[tid + off];
        __syncthreads();
    }
    const float logden = C + mx + __logf(red[0]);
    __syncthreads();

    // ---- numerator path score (gold tags) ----
    float sc = 0.f;
    const float* in_b = inputs + (size_t)b * LL * TT;
    for (int t = tid; t < LL - 1; t += TT) {
        const int pt = tags_sh[t];
        const int nt = tags_sh[t + 1];
        sc += trans[nt * TT + pt] * mf_sh[t + 1] + in_b[t * TT + pt] * mf_sh[t];
    }
    red[tid] = sc;
    __syncthreads();
#pragma unroll
    for (int off = TT / 2; off > 0; off >>= 1) {
        if (tid < off) red[tid] += red[tid + off];
        __syncthreads();
    }
    if (tid == 0) {
        const int t0 = tags_sh[0];
        const int tl = tags_sh[LL - 1];
        float score = red[0]
                    + trans[t0 * TT + START_TAG]
                    + trans[STOP_TAG * TT + tl]
                    + in_b[(LL - 1) * TT + tl] * mf_sh[LL - 1];
        g_partials[b] = score - logden;
    }

    // ---- deterministic fixed-order final reduction in the last block ----
    if (tid == 0) {
        __threadfence();
        int old = atomicAdd(&g_count, 1);
        islast = (old == (int)gridDim.x - 1);
    }
    __syncthreads();
    if (islast) {
        __threadfence();
        float s = 0.f;
#pragma unroll
        for (int k = 0; k < BB / TT; ++k)
            s += g_partials[tid * (BB / TT) + k];
        red[tid] = s;
        __syncthreads();
#pragma unroll
        for (int off = TT / 2; off > 0; off >>= 1) {
            if (tid < off) red[tid] += red[tid + off];
            __syncthreads();
        }
        if (tid == 0) {
            out[0] = red[0];
            g_count = 0;
        }
    }
}

extern "C" void kernel_launch(void* const* d_in, const int* in_sizes, int n_in,
                              void* d_out, int out_size)
{
    const float* inputs = (const float*)d_in[0];
    const int*   tags   = (const int*)d_in[1];
    const int*   mask   = (const int*)d_in[2];
    const float* trans  = (const float*)d_in[3];

    crf_fused_kernel<<<BB, TT>>>(inputs, tags, mask, trans, (float*)d_out);
}

// round 4
// speedup vs baseline: 1.3993x; 1.3993x over previous
#include <cuda_runtime.h>
#include <cstddef>

#define TT 64
#define LL 512
#define BB 512
#define START_TAG 62
#define STOP_TAG  63

// Scratch (allocation-free requirement).
__device__ float g_partials[BB];
__device__ int   g_count;          // zero-init; reset by last block each launch

__device__ __forceinline__ void fma2(unsigned long long& acc,
                                     unsigned long long p,
                                     unsigned long long q) {
    asm("fma.rn.f32x2 %0, %1, %2, %0;" : "+l"(acc) : "l"(p), "l"(q));
}
__device__ __forceinline__ void add2(unsigned long long& a, unsigned long long b) {
    asm("add.rn.f32x2 %0, %0, %1;" : "+l"(a) : "l"(b));
}
__device__ __forceinline__ float2 unpack2(unsigned long long v) {
    float2 r;
    asm("mov.b64 {%0, %1}, %2;" : "=f"(r.x), "=f"(r.y) : "l"(v));
    return r;
}
__device__ __forceinline__ unsigned long long pack2(float lo, float hi) {
    unsigned long long v;
    asm("mov.b64 %0, {%1, %2};" : "=l"(v) : "f"(lo), "f"(hi));
    return v;
}

__device__ __forceinline__ float dot64(const float* __restrict__ qbuf,
                                       const unsigned long long* __restrict__ P2) {
    const ulonglong2* q4 = (const ulonglong2*)qbuf;
    unsigned long long a0 = 0ull, a1 = 0ull, a2 = 0ull, a3 = 0ull;
#pragma unroll
    for (int k = 0; k < TT / 8; ++k) {
        ulonglong2 v = q4[2 * k];
        ulonglong2 w = q4[2 * k + 1];
        fma2(a0, P2[4 * k + 0], v.x);
        fma2(a1, P2[4 * k + 1], v.y);
        fma2(a2, P2[4 * k + 2], w.x);
        fma2(a3, P2[4 * k + 3], w.y);
    }
    add2(a0, a1);
    add2(a2, a3);
    add2(a0, a2);
    float2 sp = unpack2(a0);
    return sp.x + sp.y;
}

__global__ void __launch_bounds__(TT, 4) crf_fused_kernel(
    const float* __restrict__ inputs,   // (B, L, T)
    const int*   __restrict__ tags,     // (B, L)
    const int*   __restrict__ mask,     // (B, L)
    const float* __restrict__ trans,    // (T, T)
    float*       __restrict__ out)
{
    const int b   = blockIdx.x;
    const int tid = threadIdx.x;

    __shared__ __align__(16) float q_sh[2][TT];
    __shared__ float dslot[2];
    __shared__ float mf_sh[LL];
    __shared__ int   tags_sh[LL];
    __shared__ float red[TT];
    __shared__ int   islast;

    // Packed exp(transition) row for destination tag = tid.
    unsigned long long P2[TT / 2];
#pragma unroll
    for (int j = 0; j < TT / 2; ++j) {
        float p0 = __expf(trans[tid * TT + 2 * j]);
        float p1 = __expf(trans[tid * TT + 2 * j + 1]);
        P2[j] = pack2(p0, p1);
    }

    // Stage mask / tags; detect all-ones mask.
    int m_and = 1;
    for (int t = tid; t < LL; t += TT) {
        int m = mask[b * LL + t];
        m_and &= (m != 0);
        mf_sh[t]   = (float)m;
        tags_sh[t] = tags[b * LL + t];
    }
    if (tid == 0) { dslot[0] = 0.0f; dslot[1] = 0.0f; }
    const int all_ones = __syncthreads_and(m_and);

    const float* emit_ptr = inputs + (size_t)b * LL * TT + tid;

    float a = (tid == START_TAG) ? 0.0f : -10000.0f;  // log-alpha (general path)
    float C = 0.0f;                                   // accumulated offset

    if (all_ones) {
        // ============ fast path: prob-space recursion, MUFU-free chain ========
        // q_t[i] = (sum_j expT[i,j]*q[j]) * E_t[i] * r_t,
        // r_t = 2^-(e8(q0)-127): 3 ALU ops, exact compensation Dint += e8-127.
        q_sh[0][tid] = (tid == START_TAG) ? 1.0f : 0.0f;

        // Prefetched, pre-exponentiated emissions (4 deep) — off the chain.
        float E0 = __expf(emit_ptr[0 * TT]);
        float E1 = __expf(emit_ptr[1 * TT]);
        float E2 = __expf(emit_ptr[2 * TT]);
        float E3 = __expf(emit_ptr[3 * TT]);

        int Dint = 0;
        __syncthreads();

#pragma unroll 4
        for (int t = 0; t < LL; ++t) {
            float e_pf = (t + 4 < LL) ? emit_ptr[(t + 4) * TT] : 0.0f;
            float Epf  = __expf(e_pf);

            const int buf = t & 1;
            const float* qb = q_sh[buf];

            // Power-of-two renormalizer from q[0]'s exponent field (ALU only,
            // runs in parallel with the dot below).
            const float q0 = qb[0];
            const unsigned ebits = __float_as_uint(q0) & 0x7f800000u;
            const float r = (ebits != 0u) ? __uint_as_float(0x7f000000u - ebits)
                                          : 1.0f;
            Dint += (ebits != 0u) ? ((int)(ebits >> 23) - 127) : 0;
            const float mult = E0 * r;

            const float s = dot64(qb, P2);          // the only on-chain work
            q_sh[buf ^ 1][tid] = s * mult;
            __syncthreads();

            E0 = E1; E1 = E2; E2 = E3; E3 = Epf;
        }

        // Back to log space for the shared finale. (Dint uniform across block.)
        const float qf = q_sh[0][tid];
        a = (qf > 0.0f) ? __logf(qf) : -1.0e30f;
        C = (float)Dint * 0.6931471805599453f;
    } else {
        // ================= general masked path (log space, proven) ============
        float e_cur = emit_ptr[0];
        float e_nxt = emit_ptr[TT];
        for (int t = 0; t < LL; ++t) {
            float e_pf = (t + 2 < LL) ? emit_ptr[(t + 2) * TT] : 0.0f;

            q_sh[0][tid] = __expf(a);
            __syncthreads();

            const float mf = mf_sh[t];
            float s;
            if (mf != 0.0f) {
                s = dot64(q_sh[0], P2);
            } else {
                float acc = 0.f;
#pragma unroll
                for (int j = 0; j < TT; ++j) acc += q_sh[0][j];
                s = acc;
            }

            float d = fmaf(mf, e_cur, __logf(s));
            d = fmaxf(d, -1.0e30f);
            if (tid == 0) dslot[0] = d;
            __syncthreads();
            const float d0 = dslot[0];
            a = d - d0;
            C += d0;

            e_cur = e_nxt;
            e_nxt = e_pf;
        }
    }

    // ---- log denominator: C + logsumexp(a + trans[STOP, :]) ----
    const float term = fmaxf(a + trans[STOP_TAG * TT + tid], -1.0e30f);
    red[tid] = term;
    __syncthreads();
#pragma unroll
    for (int off = TT / 2; off > 0; off >>= 1) {
        if (tid < off) red[tid] = fmaxf(red[tid], red[tid + off]);
        __syncthreads();
    }
    const float mx = red[0];
    __syncthreads();
    red[tid] = __expf(term - mx);
    __syncthreads();
#pragma unroll
    for (int off = TT / 2; off > 0; off >>= 1) {
        if (tid < off) red[tid] += red[tid + off];
        __syncthreads();
    }
    const float logden = C + mx + __logf(red[0]);
    __syncthreads();

    // ---- numerator path score (gold tags) ----
    float sc = 0.f;
    const float* in_b = inputs + (size_t)b * LL * TT;
    for (int t = tid; t < LL - 1; t += TT) {
        const int pt = tags_sh[t];
        const int nt = tags_sh[t + 1];
        sc += trans[nt * TT + pt] * mf_sh[t + 1] + in_b[t * TT + pt] * mf_sh[t];
    }
    red[tid] = sc;
    __syncthreads();
#pragma unroll
    for (int off = TT / 2; off > 0; off >>= 1) {
        if (tid < off) red[tid] += red[tid + off];
        __syncthreads();
    }
    if (tid == 0) {
        const int t0 = tags_sh[0];
        const int tl = tags_sh[LL - 1];
        float score = red[0]
                    + trans[t0 * TT + START_TAG]
                    + trans[STOP_TAG * TT + tl]
                    + in_b[(LL - 1) * TT + tl] * mf_sh[LL - 1];
        g_partials[b] = score - logden;
    }

    // ---- deterministic fixed-order final reduction in the last block ----
    if (tid == 0) {
        __threadfence();
        int old = atomicAdd(&g_count, 1);
        islast = (old == (int)gridDim.x - 1);
    }
    __syncthreads();
    if (islast) {
        __threadfence();
        float s = 0.f;
#pragma unroll
        for (int k = 0; k < BB / TT; ++k)
            s += g_partials[tid * (BB / TT) + k];
        red[tid] = s;
        __syncthreads();
#pragma unroll
        for (int off = TT / 2; off > 0; off >>= 1) {
            if (tid < off) red[tid] += red[tid + off];
            __syncthreads();
        }
        if (tid == 0) {
            out[0] = red[0];
            g_count = 0;
        }
    }
}

extern "C" void kernel_launch(void* const* d_in, const int* in_sizes, int n_in,
                              void* d_out, int out_size)
{
    const float* inputs = (const float*)d_in[0];
    const int*   tags   = (const int*)d_in[1];
    const int*   mask   = (const int*)d_in[2];
    const float* trans  = (const float*)d_in[3];

    crf_fused_kernel<<<BB, TT>>>(inputs, tags, mask, trans, (float*)d_out);
}